// round 2
// baseline (speedup 1.0000x reference)
#include <cuda_runtime.h>
#include <math.h>

#define NN   262144
#define DIMM 256
#define NH   4
#define HD   64
#define BSEG 4096
#define SCALE 0.125f
#define EPSV 1e-8f
#define CH   32     // rows staged per chunk in main kernel
#define BT   16     // segments per block in output kernel

// ---- device scratch (static; no runtime allocation) ----
__device__ float g_wtil[NH * DIMM];      // SCALE * (q[h] dot Wk rows), folded key weights
__device__ float g_ctil[NH];             // SCALE * (q[h] dot key_b slice)
__device__ int   g_segstart[BSEG + 1];   // segment boundaries (batch is sorted)
__device__ float g_t[BSEG * NH * DIMM];  // unnormalized weighted x sums per segment (16 MB)
__device__ float g_esum[BSEG * NH];      // sum of exp(attn) per segment/head

// ---------------------------------------------------------------------------
// Kernel 1: fold query into key weights.  grid = NH blocks, 256 threads.
// w̃[h,j] = SCALE * sum_d q[h,d] * Wk[h*64+d, j]
// ---------------------------------------------------------------------------
__global__ void k_fold(const float* __restrict__ q,
                       const float* __restrict__ kw,
                       const float* __restrict__ kb) {
    int h = blockIdx.x;
    int j = threadIdx.x;
    float acc = 0.f;
#pragma unroll 8
    for (int d = 0; d < HD; d++)
        acc = fmaf(q[h * HD + d], kw[(h * HD + d) * DIMM + j], acc);
    g_wtil[h * DIMM + j] = acc * SCALE;
    if (j == 0) {
        float c = 0.f;
#pragma unroll 8
        for (int d = 0; d < HD; d++)
            c = fmaf(q[h * HD + d], kb[h * HD + d], c);
        g_ctil[h] = c * SCALE;
    }
}

// ---------------------------------------------------------------------------
// Kernel 2: segment boundaries by binary search.
// NOTE: batch is int32 on the wire (JAX x64 disabled downcasts the int64).
// ---------------------------------------------------------------------------
__global__ void k_seg(const int* __restrict__ batch) {
    int b = blockIdx.x * blockDim.x + threadIdx.x;
    if (b > BSEG) return;
    int lo = 0, hi = NN;
    while (lo < hi) {
        int mid = (lo + hi) >> 1;
        if (batch[mid] < b) lo = mid + 1; else hi = mid;
    }
    g_segstart[b] = lo;
}

// ---------------------------------------------------------------------------
// Kernel 3: main pass.  One block per segment, 256 threads.
// Single HBM pass over x: stage chunk to smem -> warp dot products (attn,
// exp) -> column-owner accumulation of t[b,h,j] = sum_n e[n,h] * x[n,j].
// ---------------------------------------------------------------------------
__global__ void __launch_bounds__(256) k_main(const float* __restrict__ x) {
    __shared__ float  sx[CH * DIMM];   // 32 KB staged x rows
    __shared__ float4 se[CH];          // exp(attn) per row (4 heads packed)
    __shared__ float  warpsum[8][4];

    const int b    = blockIdx.x;
    const int tid  = threadIdx.x;
    const int lane = tid & 31;
    const int wid  = tid >> 5;

    const int s0 = g_segstart[b];
    const int s1 = g_segstart[b + 1];

    // per-lane copies of folded weights: lane covers j = lane*4..+3 and 128+lane*4..+3
    const float4* wt4 = (const float4*)g_wtil;
    float4 w0[NH], w1[NH];
#pragma unroll
    for (int h = 0; h < NH; h++) {
        w0[h] = wt4[h * 64 + lane];
        w1[h] = wt4[h * 64 + 32 + lane];
    }
    float myct = (lane < NH) ? g_ctil[lane] : 0.f;
    float myesum = 0.f;

    float acc0 = 0.f, acc1 = 0.f, acc2 = 0.f, acc3 = 0.f;

    for (int base = s0; base < s1; base += CH) {
        const int R = min(CH, s1 - base);
        __syncthreads();  // protect smem reuse from previous chunk's phase b

        // stage: contiguous float4 copy of R rows
        {
            const float4* src = (const float4*)(x + (size_t)base * DIMM);
            float4* dst = (float4*)sx;
            for (int i = tid; i < R * 64; i += 256) dst[i] = src[i];
        }
        __syncthreads();

        // phase a: warp-per-row dot with folded weights -> exp
        {
            const float4* sx4 = (const float4*)sx;
            for (int r = wid; r < R; r += 8) {
                float4 v0 = sx4[r * 64 + lane];
                float4 v1 = sx4[r * 64 + 32 + lane];
                float a[NH];
#pragma unroll
                for (int h = 0; h < NH; h++) {
                    float t = v0.x * w0[h].x;
                    t = fmaf(v0.y, w0[h].y, t);
                    t = fmaf(v0.z, w0[h].z, t);
                    t = fmaf(v0.w, w0[h].w, t);
                    t = fmaf(v1.x, w1[h].x, t);
                    t = fmaf(v1.y, w1[h].y, t);
                    t = fmaf(v1.z, w1[h].z, t);
                    t = fmaf(v1.w, w1[h].w, t);
                    a[h] = t;
                }
#pragma unroll
                for (int h = 0; h < NH; h++) {
#pragma unroll
                    for (int o = 16; o > 0; o >>= 1)
                        a[h] += __shfl_xor_sync(0xffffffffu, a[h], o);
                }
                if (lane < NH) {
                    float av = (lane == 0) ? a[0] : (lane == 1) ? a[1]
                             : (lane == 2) ? a[2] : a[3];
                    float e = __expf(av + myct);
                    ((float*)&se[r])[lane] = e;
                    myesum += e;   // deterministic per-lane accumulation
                }
            }
        }
        __syncthreads();

        // phase b: thread owns column j = tid; accumulate 4 heads
#pragma unroll 4
        for (int r = 0; r < R; r++) {
            float  xv = sx[r * DIMM + tid];
            float4 e4 = se[r];     // LDS.128 broadcast
            acc0 = fmaf(e4.x, xv, acc0);
            acc1 = fmaf(e4.y, xv, acc1);
            acc2 = fmaf(e4.z, xv, acc2);
            acc3 = fmaf(e4.w, xv, acc3);
        }
    }

    // deterministic cross-warp reduction of exp sums
    if (lane < NH) warpsum[wid][lane] = myesum;
    __syncthreads();

    float* tout = g_t + (size_t)b * NH * DIMM;
    tout[0 * DIMM + tid] = acc0;
    tout[1 * DIMM + tid] = acc1;
    tout[2 * DIMM + tid] = acc2;
    tout[3 * DIMM + tid] = acc3;

    if (tid < NH) {
        float s = 0.f;
#pragma unroll
        for (int w = 0; w < 8; w++) s += warpsum[w][tid];
        g_esum[b * NH + tid] = s;
    }
}

// ---------------------------------------------------------------------------
// Kernel 4: out[b, h*64+d] = coef[b,h]*bv[h*64+d] + inv[b,h]*sum_j Wv[h*64+d,j]*t[b,h,j]
// grid = (BSEG/BT, NH), 256 threads. t staged in smem; Wv streamed via L1/L2.
// Uses Blackwell packed fma.rn.f32x2 (2 MACs/inst) on the j dimension.
// ---------------------------------------------------------------------------
__global__ void __launch_bounds__(256) k_out(const float* __restrict__ vw,
                                             const float* __restrict__ vb,
                                             float* __restrict__ out) {
    __shared__ float4 t_s4[BT * 64];   // 16 KB: t rows for this (b-tile, head)
    __shared__ float  inv_s[BT], coef_s[BT];

    const int h   = blockIdx.y;
    const int b0  = blockIdx.x * BT;
    const int tid = threadIdx.x;

    for (int i = tid; i < BT * 64; i += 256) {
        int row = i >> 6, c = i & 63;
        t_s4[row * 64 + c] =
            ((const float4*)g_t)[((size_t)(b0 + row) * NH + h) * 64 + c];
    }
    if (tid < BT) {
        float s  = g_esum[(b0 + tid) * NH + h];
        float iv = 1.0f / (s + EPSV);
        inv_s[tid]  = iv;
        coef_s[tid] = s * iv;   // = 0 for empty segments (s = 0)
    }
    __syncthreads();

    const int d  = tid & 63;
    const int bq = tid >> 6;   // 0..3 ; thread handles b = b0+bq+4k, k=0..3

    const ulonglong2* wrow =
        (const ulonglong2*)(vw + (size_t)(h * 64 + d) * DIMM);

    unsigned long long acc[4] = {0ull, 0ull, 0ull, 0ull};  // packed (0.f,0.f)

#pragma unroll 4
    for (int j4 = 0; j4 < 64; j4++) {
        ulonglong2 w = wrow[j4];   // LDG.128, L1-resident after first pass
#pragma unroll
        for (int k = 0; k < 4; k++) {
            ulonglong2 s = *(const ulonglong2*)&t_s4[(bq + 4 * k) * 64 + j4];
            asm("fma.rn.f32x2 %0, %1, %2, %0;" : "+l"(acc[k]) : "l"(w.x), "l"(s.x));
            asm("fma.rn.f32x2 %0, %1, %2, %0;" : "+l"(acc[k]) : "l"(w.y), "l"(s.y));
        }
    }

    const float bvv = vb[h * 64 + d];
#pragma unroll
    for (int k = 0; k < 4; k++) {
        int bb = bq + 4 * k;
        float2 p = *(float2*)&acc[k];
        float  r = p.x + p.y;
        out[(size_t)(b0 + bb) * DIMM + h * 64 + d] =
            fmaf(coef_s[bb], bvv, inv_s[bb] * r);
    }
}

// ---------------------------------------------------------------------------
extern "C" void kernel_launch(void* const* d_in, const int* in_sizes, int n_in,
                              void* d_out, int out_size) {
    const float* x     = (const float*)d_in[0];
    const int*   batch = (const int*)d_in[1];     // int32 (JAX x64 disabled)
    const float* q     = (const float*)d_in[2];
    const float* kw    = (const float*)d_in[3];
    const float* kb    = (const float*)d_in[4];
    const float* vw    = (const float*)d_in[5];
    const float* vb    = (const float*)d_in[6];
    float*       out   = (float*)d_out;

    k_fold<<<NH, 256>>>(q, kw, kb);
    k_seg<<<(BSEG + 1 + 255) / 256, 256>>>(batch);
    k_main<<<BSEG, 256>>>(x);
    k_out<<<dim3(BSEG / BT, NH), 256>>>(vw, vb, out);
}

// round 3
// speedup vs baseline: 1.7317x; 1.7317x over previous
#include <cuda_runtime.h>
#include <math.h>

#define NN   262144
#define DIMM 256
#define NH   4
#define HD   64
#define BSEG 4096
#define SCALE 0.125f
#define EPSV 1e-8f
#define CH   32     // rows staged per chunk in main kernel
#define BT   32     // segments per block in output kernel
#define WPAD 260    // padded vw row (floats): 260 mod 32 = 4 -> conflict-free LDS.128

// ---- device scratch (static; no runtime allocation) ----
__device__ float g_wtil[NH * DIMM];      // SCALE * (q[h] dot Wk rows)
__device__ float g_ctil[NH];             // SCALE * (q[h] dot key_b slice)
__device__ int   g_segstart[BSEG + 1];   // segment boundaries (batch sorted)
__device__ float g_t[BSEG * NH * DIMM];  // unnormalized weighted x sums (16 MB)
__device__ float g_esum[BSEG * NH];      // sum of exp(attn) per segment/head

// ---------------------------------------------------------------------------
__device__ __forceinline__ void cpa16(void* dst_smem, const void* src) {
    unsigned u = (unsigned)__cvta_generic_to_shared(dst_smem);
    asm volatile("cp.async.cg.shared.global [%0], [%1], 16;" :: "r"(u), "l"(src) : "memory");
}
#define CP_COMMIT() asm volatile("cp.async.commit_group;" ::: "memory")
#define CP_WAIT(n)  asm volatile("cp.async.wait_group %0;" :: "n"(n) : "memory")

// ---------------------------------------------------------------------------
// Kernel 1: fold query into key weights.  grid = NH, 256 threads.
// ---------------------------------------------------------------------------
__global__ void k_fold(const float* __restrict__ q,
                       const float* __restrict__ kw,
                       const float* __restrict__ kb) {
    int h = blockIdx.x;
    int j = threadIdx.x;
    float acc = 0.f;
#pragma unroll 8
    for (int d = 0; d < HD; d++)
        acc = fmaf(q[h * HD + d], kw[(h * HD + d) * DIMM + j], acc);
    g_wtil[h * DIMM + j] = acc * SCALE;
    if (j == 0) {
        float c = 0.f;
#pragma unroll 8
        for (int d = 0; d < HD; d++)
            c = fmaf(q[h * HD + d], kb[h * HD + d], c);
        g_ctil[h] = c * SCALE;
    }
}

// ---------------------------------------------------------------------------
// Kernel 2: segment boundaries (batch is int32, sorted).
// ---------------------------------------------------------------------------
__global__ void k_seg(const int* __restrict__ batch) {
    int b = blockIdx.x * blockDim.x + threadIdx.x;
    if (b > BSEG) return;
    int lo = 0, hi = NN;
    while (lo < hi) {
        int mid = (lo + hi) >> 1;
        if (batch[mid] < b) lo = mid + 1; else hi = mid;
    }
    g_segstart[b] = lo;
}

// ---------------------------------------------------------------------------
// Kernel 3: main pass. Block per segment, 256 threads.
// cp.async double-buffered chunks; phase a: warp dot -> exp; phase b:
// float4-column accumulation; end: smem combine across row-groups.
// dyn smem: sx 2*CH*DIMM floats (65536B) | se CH float4 (512B) | wsum 32 f
// ---------------------------------------------------------------------------
__global__ void __launch_bounds__(256, 3) k_main(const float* __restrict__ x) {
    extern __shared__ float smem[];
    float*  sx   = smem;                           // 16384 floats, 2 buffers
    float4* se   = (float4*)(smem + 2 * CH * DIMM);
    float*  wsum = (float*)(se + CH);

    const int b    = blockIdx.x;
    const int tid  = threadIdx.x;
    const int lane = tid & 31;
    const int wid  = tid >> 5;

    const int s0  = g_segstart[b];
    const int s1  = g_segstart[b + 1];
    const int nch = (s1 - s0 + CH - 1) / CH;

    // folded weights: lane covers j = lane*4..+3 and 128+lane*4..+3
    const float4* wt4 = (const float4*)g_wtil;
    float4 w0[NH], w1[NH];
#pragma unroll
    for (int h = 0; h < NH; h++) {
        w0[h] = wt4[h * 64 + lane];
        w1[h] = wt4[h * 64 + 32 + lane];
    }
    const float ct = g_ctil[lane >> 3];

    const int c_col = tid & 63;   // float4 column owned in phase b
    const int r4    = tid >> 6;   // row group (r = r4, r4+4, ...)

    float  myesum = 0.f;
    float4 acc[NH];
#pragma unroll
    for (int h = 0; h < NH; h++) acc[h] = make_float4(0.f, 0.f, 0.f, 0.f);

    // prologue: issue chunk 0
    if (nch > 0) {
        const int R0 = min(CH, s1 - s0);
        const float4* src = (const float4*)(x + (size_t)s0 * DIMM);
        float4* dst = (float4*)sx;
        for (int i = tid; i < R0 * 64; i += 256) cpa16(&dst[i], &src[i]);
        CP_COMMIT();
    }

    for (int cc = 0; cc < nch; cc++) {
        if (cc + 1 < nch) {   // issue next chunk into other buffer
            const int base2 = s0 + (cc + 1) * CH;
            const int R2 = min(CH, s1 - base2);
            const float4* src = (const float4*)(x + (size_t)base2 * DIMM);
            float4* dst = (float4*)(sx + ((cc + 1) & 1) * CH * DIMM);
            for (int i = tid; i < R2 * 64; i += 256) cpa16(&dst[i], &src[i]);
            CP_COMMIT();
            CP_WAIT(1);
        } else {
            CP_WAIT(0);
        }
        __syncthreads();

        const int R = min(CH, s1 - (s0 + cc * CH));
        const float4* sx4 = (const float4*)(sx + (cc & 1) * CH * DIMM);

        // ---- phase a: warp per row -> attn dot, exp ----
        for (int r = wid; r < R; r += 8) {
            float4 v0 = sx4[r * 64 + lane];
            float4 v1 = sx4[r * 64 + 32 + lane];
            float a0, a1, a2, a3;
            {
                float t;
                t = v0.x*w0[0].x; t = fmaf(v0.y,w0[0].y,t); t = fmaf(v0.z,w0[0].z,t); t = fmaf(v0.w,w0[0].w,t);
                t = fmaf(v1.x,w1[0].x,t); t = fmaf(v1.y,w1[0].y,t); t = fmaf(v1.z,w1[0].z,t); t = fmaf(v1.w,w1[0].w,t);
                a0 = t;
                t = v0.x*w0[1].x; t = fmaf(v0.y,w0[1].y,t); t = fmaf(v0.z,w0[1].z,t); t = fmaf(v0.w,w0[1].w,t);
                t = fmaf(v1.x,w1[1].x,t); t = fmaf(v1.y,w1[1].y,t); t = fmaf(v1.z,w1[1].z,t); t = fmaf(v1.w,w1[1].w,t);
                a1 = t;
                t = v0.x*w0[2].x; t = fmaf(v0.y,w0[2].y,t); t = fmaf(v0.z,w0[2].z,t); t = fmaf(v0.w,w0[2].w,t);
                t = fmaf(v1.x,w1[2].x,t); t = fmaf(v1.y,w1[2].y,t); t = fmaf(v1.z,w1[2].z,t); t = fmaf(v1.w,w1[2].w,t);
                a2 = t;
                t = v0.x*w0[3].x; t = fmaf(v0.y,w0[3].y,t); t = fmaf(v0.z,w0[3].z,t); t = fmaf(v0.w,w0[3].w,t);
                t = fmaf(v1.x,w1[3].x,t); t = fmaf(v1.y,w1[3].y,t); t = fmaf(v1.z,w1[3].z,t); t = fmaf(v1.w,w1[3].w,t);
                a3 = t;
            }
            // fold 16, 8 on all heads -> partials per (lane mod 8)
#pragma unroll
            for (int o = 16; o >= 8; o >>= 1) {
                a0 += __shfl_xor_sync(0xffffffffu, a0, o);
                a1 += __shfl_xor_sync(0xffffffffu, a1, o);
                a2 += __shfl_xor_sync(0xffffffffu, a2, o);
                a3 += __shfl_xor_sync(0xffffffffu, a3, o);
            }
            // lane's head = lane>>3 ; finish within 8-lane group
            float val = (lane < 8) ? a0 : (lane < 16) ? a1 : (lane < 24) ? a2 : a3;
            val += __shfl_xor_sync(0xffffffffu, val, 4);
            val += __shfl_xor_sync(0xffffffffu, val, 2);
            val += __shfl_xor_sync(0xffffffffu, val, 1);
            if ((lane & 7) == 0) {
                float e = __expf(val + ct);
                ((float*)&se[r])[lane >> 3] = e;
                myesum += e;
            }
        }
        __syncthreads();

        // ---- phase b: thread owns float4 column, rows strided by 4 ----
        for (int r = r4; r < R; r += 4) {
            float4 xv = sx4[r * 64 + c_col];
            float4 e4 = se[r];   // broadcast
            acc[0].x = fmaf(e4.x, xv.x, acc[0].x); acc[0].y = fmaf(e4.x, xv.y, acc[0].y);
            acc[0].z = fmaf(e4.x, xv.z, acc[0].z); acc[0].w = fmaf(e4.x, xv.w, acc[0].w);
            acc[1].x = fmaf(e4.y, xv.x, acc[1].x); acc[1].y = fmaf(e4.y, xv.y, acc[1].y);
            acc[1].z = fmaf(e4.y, xv.z, acc[1].z); acc[1].w = fmaf(e4.y, xv.w, acc[1].w);
            acc[2].x = fmaf(e4.z, xv.x, acc[2].x); acc[2].y = fmaf(e4.z, xv.y, acc[2].y);
            acc[2].z = fmaf(e4.z, xv.z, acc[2].z); acc[2].w = fmaf(e4.z, xv.w, acc[2].w);
            acc[3].x = fmaf(e4.w, xv.x, acc[3].x); acc[3].y = fmaf(e4.w, xv.y, acc[3].y);
            acc[3].z = fmaf(e4.w, xv.z, acc[3].z); acc[3].w = fmaf(e4.w, xv.w, acc[3].w);
        }
        __syncthreads();
    }

    // combine acc across the 4 row groups via smem scratch (reuse sx)
    float4* sacc = (float4*)sx;
#pragma unroll
    for (int h = 0; h < NH; h++)
        sacc[(r4 * 4 + h) * 64 + c_col] = acc[h];
    if ((lane & 7) == 0) wsum[wid * 4 + (lane >> 3)] = myesum;
    __syncthreads();

    {
        const int ho = tid >> 6, co = tid & 63;
        float4 t0 = sacc[(0 * 4 + ho) * 64 + co];
        float4 t1 = sacc[(1 * 4 + ho) * 64 + co];
        float4 t2 = sacc[(2 * 4 + ho) * 64 + co];
        float4 t3 = sacc[(3 * 4 + ho) * 64 + co];
        float4 s;
        s.x = (t0.x + t1.x) + (t2.x + t3.x);
        s.y = (t0.y + t1.y) + (t2.y + t3.y);
        s.z = (t0.z + t1.z) + (t2.z + t3.z);
        s.w = (t0.w + t1.w) + (t2.w + t3.w);
        ((float4*)(g_t + (size_t)b * NH * DIMM))[ho * 64 + co] = s;
    }
    if (tid < NH) {
        float s = 0.f;
#pragma unroll
        for (int w = 0; w < 8; w++) s += wsum[w * 4 + tid];
        g_esum[b * NH + tid] = s;
    }
}

// ---------------------------------------------------------------------------
// Kernel 4: out[b, h*64+d] via smem-staged vw slice (padded rows: no strided
// LDG replays) and t tile.  grid = (BSEG/BT, NH), 256 threads.
// dyn smem: sw 64*WPAD floats (66560B) | t4 BT*64 float4 (32768B) | inv,coef
// ---------------------------------------------------------------------------
__global__ void __launch_bounds__(256) k_out(const float* __restrict__ vw,
                                             const float* __restrict__ vb,
                                             float* __restrict__ out) {
    extern __shared__ float sm[];
    float*  sw     = sm;                                // 64 x WPAD
    float4* t4     = (float4*)(sm + 64 * WPAD);         // BT x 64
    float*  inv_s  = sm + 64 * WPAD + BT * 64 * 4;
    float*  coef_s = inv_s + BT;

    const int h   = blockIdx.y;
    const int b0  = blockIdx.x * BT;
    const int tid = threadIdx.x;

    // stage vw head slice, padded rows (conflict-free LDS.128 later)
    {
        const float4* vw4 = (const float4*)(vw + (size_t)h * 64 * DIMM);
        for (int i = tid; i < 64 * 64; i += 256) {
            int d = i >> 6, c = i & 63;
            *(float4*)(sw + d * WPAD + c * 4) = vw4[i];
        }
    }
    // stage t tile
    for (int i = tid; i < BT * 64; i += 256) {
        int row = i >> 6, c = i & 63;
        t4[row * 64 + c] = ((const float4*)g_t)[((size_t)(b0 + row) * NH + h) * 64 + c];
    }
    if (tid < BT) {
        float s  = g_esum[(b0 + tid) * NH + h];
        float iv = 1.0f / (s + EPSV);
        inv_s[tid]  = iv;
        coef_s[tid] = s * iv;   // 0 for empty segments
    }
    __syncthreads();

    const int d  = tid & 63;
    const int bq = tid >> 6;   // thread handles b = b0 + bq + 4k, k=0..7

    const ulonglong2* wrow = (const ulonglong2*)(sw + d * WPAD);

    unsigned long long acc[8] = {0ull,0ull,0ull,0ull,0ull,0ull,0ull,0ull};

#pragma unroll 4
    for (int j4 = 0; j4 < 64; j4++) {
        ulonglong2 w = wrow[j4];   // LDS.128, bank-conflict-free via WPAD
#pragma unroll
        for (int k = 0; k < 8; k++) {
            ulonglong2 s = *(const ulonglong2*)&t4[(bq + 4 * k) * 64 + j4];  // broadcast
            asm("fma.rn.f32x2 %0, %1, %2, %0;" : "+l"(acc[k]) : "l"(w.x), "l"(s.x));
            asm("fma.rn.f32x2 %0, %1, %2, %0;" : "+l"(acc[k]) : "l"(w.y), "l"(s.y));
        }
    }

    const float bvv = vb[h * 64 + d];
#pragma unroll
    for (int k = 0; k < 8; k++) {
        int bb = bq + 4 * k;
        float2 p = *(float2*)&acc[k];
        float  r = p.x + p.y;
        out[(size_t)(b0 + bb) * DIMM + h * 64 + d] =
            fmaf(coef_s[bb], bvv, inv_s[bb] * r);
    }
}

// ---------------------------------------------------------------------------
extern "C" void kernel_launch(void* const* d_in, const int* in_sizes, int n_in,
                              void* d_out, int out_size) {
    const float* x     = (const float*)d_in[0];
    const int*   batch = (const int*)d_in[1];
    const float* q     = (const float*)d_in[2];
    const float* kw    = (const float*)d_in[3];
    const float* kb    = (const float*)d_in[4];
    const float* vw    = (const float*)d_in[5];
    const float* vb    = (const float*)d_in[6];
    float*       out   = (float*)d_out;

    const int smem_main = 2 * CH * DIMM * 4 + CH * 16 + 32 * 4;          // 66176
    const int smem_out  = 64 * WPAD * 4 + BT * 64 * 16 + 2 * BT * 4;     // 99584
    cudaFuncSetAttribute(k_main, cudaFuncAttributeMaxDynamicSharedMemorySize, smem_main);
    cudaFuncSetAttribute(k_out,  cudaFuncAttributeMaxDynamicSharedMemorySize, smem_out);

    k_fold<<<NH, 256>>>(q, kw, kb);
    k_seg<<<(BSEG + 1 + 255) / 256, 256>>>(batch);
    k_main<<<BSEG, 256, smem_main>>>(x);
    k_out<<<dim3(BSEG / BT, NH), 256, smem_out>>>(vw, vb, out);
}